// round 15
// baseline (speedup 1.0000x reference)
#include <cuda_runtime.h>
#include <math.h>

#define N_ITER 10
#define UPD_CHUNK 24

static __device__ float d_p[5];                     // separable 1D psf
static __device__ float d_q[9];                     // q = p (*) p  (9-tap)
static __device__ float d_E[96 * 192 * 192];        // conv_xy(residual) planes
static __device__ float d_A[192 * 192 * 192];       // ping
static __device__ float d_B[192 * 192 * 192];       // spec: S~ ; gen: pong

// ---------------------------------------------------------------------------
// packed f32x2 helpers (Blackwell)
// ---------------------------------------------------------------------------
__device__ __forceinline__ unsigned long long pk2(float lo, float hi) {
    unsigned long long r;
    asm("mov.b64 %0, {%1, %2};" : "=l"(r) : "f"(lo), "f"(hi));
    return r;
}
__device__ __forceinline__ unsigned long long as2(float2 v) {
    // free reinterpret: float2 from LDS.64 is already an aligned register pair
    return *reinterpret_cast<unsigned long long*>(&v);
}
__device__ __forceinline__ void upk2(unsigned long long v, float& lo, float& hi) {
    asm("mov.b64 {%0, %1}, %2;" : "=f"(lo), "=f"(hi) : "l"(v));
}
__device__ __forceinline__ unsigned long long fma2_(unsigned long long a,
                                                    unsigned long long b,
                                                    unsigned long long c) {
    unsigned long long d;
    asm("fma.rn.f32x2 %0, %1, %2, %3;" : "=l"(d) : "l"(a), "l"(b), "l"(c));
    return d;
}
__device__ __forceinline__ unsigned long long mul2_(unsigned long long a,
                                                    unsigned long long b) {
    unsigned long long d;
    asm("mul.rn.f32x2 %0, %1, %2;" : "=l"(d) : "l"(a), "l"(b));
    return d;
}

// ---------------------------------------------------------------------------
__global__ void init_p_kernel(const float* __restrict__ psf) {
    if (threadIdx.x == 0) {
        float p[5];
        for (int i = 0; i < 5; ++i) {
            float s = 0.f;
            for (int j = 0; j < 25; ++j) s += psf[i * 25 + j];
            p[i] = s;
            d_p[i] = s;
        }
        for (int i = 0; i < 9; ++i) {
            float s = 0.f;
            for (int a = 0; a < 5; ++a) {
                int b = i - a;
                if (b >= 0 && b < 5) s += p[a] * p[b];
            }
            d_q[i] = s;
        }
    }
}

// ===========================================================================
// S~ = conv_p2d(slices), computed ONCE per launch. spec dims (H,W mult of 32).
// ===========================================================================
template <int H, int W>
__global__ __launch_bounds__(256) void stilde_t(
    const float* __restrict__ slices, float* __restrict__ St) {
    constexpr int HW = H * W;
    __shared__ float sIn[36][38];
    __shared__ float sMid[36][33];

    const int i = blockIdx.z;
    const int x0 = blockIdx.x * 32, y0 = blockIdx.y * 32;
    const int tx = threadIdx.x, ty = threadIdx.y;
    const float p0 = d_p[0], p1 = d_p[1], p2 = d_p[2], p3 = d_p[3], p4 = d_p[4];
    const float* sl = slices + i * HW;

    #pragma unroll
    for (int k = 0; k < 5; ++k) {
        const int r = (k < 4) ? (ty + 8 * k) : (32 + ty);
        if (k == 4 && ty >= 4) break;
        const int gy = y0 - 2 + r;
        const bool okY = (unsigned)gy < (unsigned)H;
        #pragma unroll
        for (int b = 0; b < 2; ++b) {
            if (b == 1 && tx >= 4) break;
            const int c = b * 32 + tx;
            const int gx = x0 - 2 + c;
            sIn[r][c] = (okY && (unsigned)gx < (unsigned)W) ? sl[gy * W + gx] : 0.f;
        }
    }
    __syncthreads();

    #pragma unroll
    for (int k = 0; k < 5; ++k) {
        const int r = (k < 4) ? (ty + 8 * k) : (32 + ty);
        if (k == 4 && ty >= 4) break;
        sMid[r][tx] = p0 * sIn[r][tx]     + p1 * sIn[r][tx + 1] + p2 * sIn[r][tx + 2]
                    + p3 * sIn[r][tx + 3] + p4 * sIn[r][tx + 4];
    }
    __syncthreads();

    float* Si = St + i * HW + y0 * W + x0;
    #pragma unroll
    for (int k = 0; k < 4; ++k) {
        const int r = ty + 8 * k;
        Si[r * W + tx] = p0 * sMid[r][tx]     + p1 * sMid[r + 1][tx]
                       + p2 * sMid[r + 2][tx] + p3 * sMid[r + 3][tx]
                       + p4 * sMid[r + 4][tx];
    }
}

// ===========================================================================
// fused_E v3 (spec) — unchanged from validated R12/R13.
// ===========================================================================
template <int D, int H, int W, int NS>
__global__ __launch_bounds__(256, 5) void fused_E3_t(
    const float* __restrict__ x, const float* __restrict__ St,
    float* __restrict__ E, const int* __restrict__ stridep) {
    constexpr int HW = H * W;
    __shared__ float bufZ[2][40][42];
    __shared__ float bufA[2][40][37];

    const int pr = blockIdx.z;
    const int stride = *stridep;
    const int iA = 2 * pr;
    const int ziA = iA * stride;
    const int x0 = blockIdx.x * 32, y0 = blockIdx.y * 32;
    const int tx = threadIdx.x, ty = threadIdx.y;

    const float p0 = d_p[0], p1 = d_p[1], p2 = d_p[2], p3 = d_p[3], p4 = d_p[4];

    const bool intXY = (x0 >= 4) && (x0 + 36 <= W) && (y0 >= 4) && (y0 + 36 <= H);
    const bool interior = (x0 >= 2) && (x0 + 34 <= W) && (y0 >= 2) && (y0 + 34 <= H);

    if (stride == 2) {
        const int q0 = ziA - 2;
        const bool intZ = (q0 >= 0) && (ziA + 4 < D);
        if (intZ && intXY) {
            const float* base = x + q0 * HW + (y0 - 4) * W + (x0 - 4);
            #pragma unroll
            for (int k = 0; k < 5; ++k) {
                const int r = ty + 8 * k;
                const float* rowp = base + r * W;
                #pragma unroll
                for (int b = 0; b < 2; ++b) {
                    if (b == 1 && tx >= 8) break;
                    const int c = b * 32 + tx;
                    const float* col = rowp + c;
                    const float v0 = col[0],      v1 = col[HW],     v2 = col[2 * HW];
                    const float v3 = col[3 * HW], v4 = col[4 * HW], v5 = col[5 * HW];
                    const float v6 = col[6 * HW];
                    bufZ[0][r][c] = p0 * v0 + p1 * v1 + p2 * v2 + p3 * v3 + p4 * v4;
                    bufZ[1][r][c] = p0 * v2 + p1 * v3 + p2 * v4 + p3 * v5 + p4 * v6;
                }
            }
        } else {
            bool qok[7];
            #pragma unroll
            for (int j = 0; j < 7; ++j) qok[j] = (unsigned)(q0 + j) < (unsigned)D;
            #pragma unroll
            for (int k = 0; k < 5; ++k) {
                const int r = ty + 8 * k;
                const int gy = y0 - 4 + r;
                const bool okY = (unsigned)gy < (unsigned)H;
                #pragma unroll
                for (int b = 0; b < 2; ++b) {
                    if (b == 1 && tx >= 8) break;
                    const int c = b * 32 + tx;
                    const int gx = x0 - 4 + c;
                    const bool okXY = okY && (unsigned)gx < (unsigned)W;
                    const float* col = x + gy * W + gx;
                    float v[7];
                    #pragma unroll
                    for (int j = 0; j < 7; ++j)
                        v[j] = (okXY && qok[j]) ? col[(q0 + j) * HW] : 0.f;
                    bufZ[0][r][c] = p0 * v[0] + p1 * v[1] + p2 * v[2] + p3 * v[3] + p4 * v[4];
                    bufZ[1][r][c] = p0 * v[2] + p1 * v[3] + p2 * v[4] + p3 * v[5] + p4 * v[6];
                }
            }
        }
    } else {
        #pragma unroll
        for (int s = 0; s < 2; ++s) {
            const int zi = (iA + s) * stride;
            const int z0 = zi - 2;
            bool zok[5];
            #pragma unroll
            for (int j = 0; j < 5; ++j) zok[j] = (unsigned)(z0 + j) < (unsigned)D;
            #pragma unroll
            for (int k = 0; k < 5; ++k) {
                const int r = ty + 8 * k;
                const int gy = y0 - 4 + r;
                const bool okY = (unsigned)gy < (unsigned)H;
                #pragma unroll
                for (int b = 0; b < 2; ++b) {
                    if (b == 1 && tx >= 8) break;
                    const int c = b * 32 + tx;
                    const int gx = x0 - 4 + c;
                    const bool okXY = okY && (unsigned)gx < (unsigned)W;
                    const float* col = x + gy * W + gx;
                    float acc = 0.f;
                    if (okXY) {
                        if (zok[0]) acc = fmaf(p0, col[(z0 + 0) * HW], acc);
                        if (zok[1]) acc = fmaf(p1, col[(z0 + 1) * HW], acc);
                        if (zok[2]) acc = fmaf(p2, col[(z0 + 2) * HW], acc);
                        if (zok[3]) acc = fmaf(p3, col[(z0 + 3) * HW], acc);
                        if (zok[4]) acc = fmaf(p4, col[(z0 + 4) * HW], acc);
                    }
                    bufZ[s][r][c] = acc;
                }
            }
        }
    }
    __syncthreads();

    if (interior) {
        const float q0_ = d_q[0], q1_ = d_q[1], q2_ = d_q[2], q3_ = d_q[3];
        const float q4_ = d_q[4], q5_ = d_q[5], q6_ = d_q[6], q7_ = d_q[7];
        const float q8_ = d_q[8];

        #pragma unroll
        for (int s = 0; s < 2; ++s) {
            #pragma unroll
            for (int k = 0; k < 5; ++k) {
                const int r = ty + 8 * k;
                const float* zr = &bufZ[s][r][tx];
                bufA[s][r][tx] = q0_ * zr[0] + q1_ * zr[1] + q2_ * zr[2]
                               + q3_ * zr[3] + q4_ * zr[4] + q5_ * zr[5]
                               + q6_ * zr[6] + q7_ * zr[7] + q8_ * zr[8];
            }
        }
        __syncthreads();

        #pragma unroll
        for (int s = 0; s < 2; ++s) {
            float* Ei = E + (iA + s) * HW + y0 * W + x0;
            const float* Si = St + (iA + s) * HW + y0 * W + x0;
            #pragma unroll
            for (int k = 0; k < 4; ++k) {
                const int r = ty + 8 * k;
                float v = q0_ * bufA[s][r][tx]     + q1_ * bufA[s][r + 1][tx]
                        + q2_ * bufA[s][r + 2][tx] + q3_ * bufA[s][r + 3][tx]
                        + q4_ * bufA[s][r + 4][tx] + q5_ * bufA[s][r + 5][tx]
                        + q6_ * bufA[s][r + 6][tx] + q7_ * bufA[s][r + 7][tx]
                        + q8_ * bufA[s][r + 8][tx];
                Ei[r * W + tx] = v - Si[r * W + tx];
            }
        }
        return;
    }

    #pragma unroll
    for (int s = 0; s < 2; ++s) {
        #pragma unroll
        for (int k = 0; k < 5; ++k) {
            const int r = ty + 8 * k;
            bufA[s][r][tx] = p0 * bufZ[s][r][tx]     + p1 * bufZ[s][r][tx + 1]
                           + p2 * bufZ[s][r][tx + 2] + p3 * bufZ[s][r][tx + 3]
                           + p4 * bufZ[s][r][tx + 4];
            if (tx < 4) {
                const int c = 32 + tx;
                bufA[s][r][c] = p0 * bufZ[s][r][c]     + p1 * bufZ[s][r][c + 1]
                              + p2 * bufZ[s][r][c + 2] + p3 * bufZ[s][r][c + 3]
                              + p4 * bufZ[s][r][c + 4];
            }
        }
    }
    __syncthreads();

    {
        float (*sF0)[37] = (float (*)[37]) &bufZ[0][0][0];
        float (*sF1)[37] = (float (*)[37]) &bufZ[1][0][0];
        #pragma unroll
        for (int s = 0; s < 2; ++s) {
            float (*sF)[37] = s ? sF1 : sF0;
            #pragma unroll
            for (int k = 0; k < 5; ++k) {
                const int r = (k < 4) ? (ty + 8 * k) : (32 + ty);
                if (k == 4 && ty >= 4) break;
                const int gy = y0 - 2 + r;
                const bool okY = (unsigned)gy < (unsigned)H;
                #pragma unroll
                for (int b = 0; b < 2; ++b) {
                    if (b == 1 && tx >= 4) break;
                    const int c = b * 32 + tx;
                    const int gx = x0 - 2 + c;
                    float v = 0.f;
                    if (okY && (unsigned)gx < (unsigned)W) {
                        v = p0 * bufA[s][r][c]     + p1 * bufA[s][r + 1][c]
                          + p2 * bufA[s][r + 2][c] + p3 * bufA[s][r + 3][c]
                          + p4 * bufA[s][r + 4][c];
                    }
                    sF[r][c] = v;
                }
            }
        }
    }
    __syncthreads();

    {
        float (*sF0)[37] = (float (*)[37]) &bufZ[0][0][0];
        float (*sF1)[37] = (float (*)[37]) &bufZ[1][0][0];
        float (*sB0)[33] = (float (*)[33]) &bufA[0][0][0];
        float (*sB1)[33] = (float (*)[33]) &bufA[1][0][0];
        #pragma unroll
        for (int s = 0; s < 2; ++s) {
            float (*sF)[37] = s ? sF1 : sF0;
            float (*sB)[33] = s ? sB1 : sB0;
            #pragma unroll
            for (int k = 0; k < 5; ++k) {
                const int r = (k < 4) ? (ty + 8 * k) : (32 + ty);
                if (k == 4 && ty >= 4) break;
                sB[r][tx] = p0 * sF[r][tx]     + p1 * sF[r][tx + 1] + p2 * sF[r][tx + 2]
                          + p3 * sF[r][tx + 3] + p4 * sF[r][tx + 4];
            }
        }
    }
    __syncthreads();

    {
        float (*sB0)[33] = (float (*)[33]) &bufA[0][0][0];
        float (*sB1)[33] = (float (*)[33]) &bufA[1][0][0];
        #pragma unroll
        for (int s = 0; s < 2; ++s) {
            float (*sB)[33] = s ? sB1 : sB0;
            float* Ei = E + (iA + s) * HW + y0 * W + x0;
            const float* Si = St + (iA + s) * HW + y0 * W + x0;
            #pragma unroll
            for (int k = 0; k < 4; ++k) {
                const int r = ty + 8 * k;
                float v = p0 * sB[r][tx]     + p1 * sB[r + 1][tx]
                        + p2 * sB[r + 2][tx] + p3 * sB[r + 3][tx]
                        + p4 * sB[r + 4][tx];
                Ei[r * W + tx] = v - Si[r * W + tx];
            }
        }
    }
}

// ===========================================================================
// update v4 (spec): float2 z-pair smem ring; packed operands taken directly
// from LDS.64 register pairs for dz=+-1 (no packing movs); pk2 only for dz=0.
// ===========================================================================
template <int D, int H, int W, int NS>
__global__ __launch_bounds__(256, 5) void update4_t(
    const float* __restrict__ xin, const float* __restrict__ E,
    float* __restrict__ xout, const int* __restrict__ stridep, int do_relu) {
    constexpr int HW = H * W;
    __shared__ float2 sp[3][10][36];

    const int x0 = blockIdx.x * 32, y0 = blockIdx.y * 8;
    const int zb = blockIdx.z * UPD_CHUNK;        // even
    const int tx = threadIdx.x, ty = threadIdx.y;
    const int tid = ty * 32 + tx;
    const int y = y0 + ty, x = x0 + tx;
    const int stride = *stridep;

    const float p0 = d_p[0], p1 = d_p[1], p2 = d_p[2], p3 = d_p[3], p4 = d_p[4];

    const float w1 = (float)(1.0 / (1.0 * 0.1 * 0.1));
    const float w2 = (float)(1.0 / (2.0 * 0.1 * 0.1));
    const float w3 = (float)(1.0 / (3.0 * 0.1 * 0.1));

    // hoisted cooperative-load geometry (10*34 = 340 slots)
    const int ly0 = tid / 34, lx0 = tid % 34;
    const int gy0 = y0 - 1 + ly0, gx0 = x0 - 1 + lx0;
    const bool ok0 = (unsigned)gy0 < (unsigned)H && (unsigned)gx0 < (unsigned)W;
    const int off0 = ok0 ? (gy0 * W + gx0) : 0;

    const int i1 = tid + 256;
    const bool has1 = (i1 < 340);
    const int ly1 = has1 ? i1 / 34 : 0, lx1 = has1 ? i1 % 34 : 0;
    const int gy1 = y0 - 1 + ly1, gx1 = x0 - 1 + lx1;
    const bool ok1 = has1 && (unsigned)gy1 < (unsigned)H && (unsigned)gx1 < (unsigned)W;
    const int off1 = ok1 ? (gy1 * W + gx1) : 0;

    auto loadPair = [&](int k, int buf) {
        const int za = zb - 1 + 2 * k, zbp = zb + 2 * k;
        const bool zaok = (unsigned)za < (unsigned)D;
        const bool zbok = (unsigned)zbp < (unsigned)D;
        const int zoA = (zaok ? za : 0) * HW;
        const int zoB = (zbok ? zbp : 0) * HW;
        {
            float a = (zaok && ok0) ? xin[zoA + off0] : 0.f;
            float b = (zbok && ok0) ? xin[zoB + off0] : 0.f;
            sp[buf][ly0][lx0] = make_float2(a, b);
        }
        if (has1) {
            float a = (zaok && ok1) ? xin[zoA + off1] : 0.f;
            float b = (zbok && ok1) ? xin[zoB + off1] : 0.f;
            sp[buf][ly1][lx1] = make_float2(a, b);
        }
    };

    loadPair(0, 0);
    loadPair(1, 1);
    __syncthreads();

    const bool interior_xy = (y > 0 && y < H - 1 && x > 0 && x < W - 1);
    const int eo = y * W + x;
    const float* Ecol = E + eo;
    float* outcol = xout + eo;
    const float ALPHA = 0.5f;
    const float BETA = (float)(0.02 * 0.1 * 0.1);

    const unsigned long long w1p = pk2(w1, w1);
    const unsigned long long w2p = pk2(w2, w2);
    const unsigned long long w3p = pk2(w3, w3);
    const unsigned long long one2 = pk2(1.0f, 1.0f);
    const unsigned long long m12  = pk2(-1.0f, -1.0f);

    if (stride == 2) {
        int h = zb >> 1;
        float eA = (h >= 1) ? Ecol[(h - 1) * HW] : 0.f;
        float eB = (h < NS) ? Ecol[h * HW] : 0.f;
        float eC = (h + 1 < NS) ? Ecol[(h + 1) * HW] : 0.f;

        #pragma unroll 2
        for (int t = 0; t < UPD_CHUNK / 2; ++t, ++h) {
            const int z = zb + 2 * t;
            loadPair(t + 2, (t + 2) % 3);       // planes z+3, z+4
            const int b0i = t % 3, b1i = (t + 1) % 3;

            const float2 c0 = sp[b0i][ty + 1][tx + 1];   // (z-1, z)
            const float2 c1 = sp[b1i][ty + 1][tx + 1];   // (z+1, z+2)

            float ge = 0.f, go = 0.f;
            if (interior_xy) {
                const unsigned long long v0p = pk2(c0.y, c1.x);
                unsigned long long acc = pk2(0.0f, 0.0f);
                #pragma unroll
                for (int j = 0; j < 9; ++j) {
                    const int jy = j / 3, jx = j % 3;
                    const int dy = jy - 1, dx = jx - 1;
                    const int d2 = dy * dy + dx * dx;
                    const unsigned long long wa =
                        (d2 == 0) ? w1p : ((d2 == 1) ? w2p : w3p);
                    const float2 m  = sp[b0i][ty + jy][tx + jx];
                    const float2 pp = sp[b1i][ty + jy][tx + jx];
                    {   // dz = -1 : operand IS the loaded pair (m.x, m.y)
                        const unsigned long long dv = fma2_(as2(m), m12, v0p);
                        const unsigned long long tt = mul2_(dv, wa);
                        const unsigned long long ar = fma2_(dv, tt, one2);
                        float a0, a1; upk2(ar, a0, a1);
                        acc = fma2_(tt, pk2(rsqrtf(a0), rsqrtf(a1)), acc);
                    }
                    {   // dz = +1 : operand IS the loaded pair (pp.x, pp.y)
                        const unsigned long long dv = fma2_(as2(pp), m12, v0p);
                        const unsigned long long tt = mul2_(dv, wa);
                        const unsigned long long ar = fma2_(dv, tt, one2);
                        float a0, a1; upk2(ar, a0, a1);
                        acc = fma2_(tt, pk2(rsqrtf(a0), rsqrtf(a1)), acc);
                    }
                    if (j != 4) {  // dz = 0 : crosses pairs -> real pack
                        const unsigned long long wb = (d2 == 1) ? w1p : w2p;
                        const unsigned long long np = pk2(m.y, pp.x);
                        const unsigned long long dv = fma2_(np, m12, v0p);
                        const unsigned long long tt = mul2_(dv, wb);
                        const unsigned long long ar = fma2_(dv, tt, one2);
                        float a0, a1; upk2(ar, a0, a1);
                        acc = fma2_(tt, pk2(rsqrtf(a0), rsqrtf(a1)), acc);
                    }
                }
                upk2(acc, ge, go);
                if (z == 0) ge = 0.f;
                if (z + 1 == D - 1) go = 0.f;
            }

            // ---- even z ----
            {
                float gd = fmaf(p0, eA, fmaf(p2, eB, p4 * eC));
                float xn = c0.y - ALPHA * (gd + BETA * ge);
                if (do_relu) xn = fmaxf(xn, 0.f);
                outcol[z * HW] = xn;
            }
            // ---- odd z+1 ----
            {
                float gd = fmaf(p1, eB, p3 * eC);
                float xn = c1.x - ALPHA * (gd + BETA * go);
                if (do_relu) xn = fmaxf(xn, 0.f);
                outcol[(z + 1) * HW] = xn;
            }

            eA = eB; eB = eC;
            eC = (h + 2 < NS) ? Ecol[(h + 2) * HW] : 0.f;
            __syncthreads();
        }
    } else {
        for (int t = 0; t < UPD_CHUNK / 2; ++t) {
            const int z = zb + 2 * t;
            loadPair(t + 2, (t + 2) % 3);
            const int b0i = t % 3, b1i = (t + 1) % 3;

            #pragma unroll
            for (int s = 0; s < 2; ++s) {
                const int zz0 = z + s;
                float ge = 0.f;
                const float2 cc0 = sp[b0i][ty + 1][tx + 1];
                const float2 cc1 = sp[b1i][ty + 1][tx + 1];
                const float v0 = s ? cc1.x : cc0.y;
                if (interior_xy && zz0 > 0 && zz0 < D - 1) {
                    #pragma unroll
                    for (int j = 0; j < 9; ++j) {
                        const int jy = j / 3, jx = j % 3;
                        const int dy = jy - 1, dx = jx - 1;
                        const int d2 = dy * dy + dx * dx;
                        const float wa = (d2 == 0) ? w1 : ((d2 == 1) ? w2 : w3);
                        const float2 m  = sp[b0i][ty + jy][tx + jx];
                        const float2 pp = sp[b1i][ty + jy][tx + jx];
                        const float Av = s ? m.y : m.x;
                        const float Bv = s ? pp.x : m.y;
                        const float Cv = s ? pp.y : pp.x;
                        { float dv = v0 - Av; float tt = dv * wa; ge += tt * rsqrtf(fmaf(dv, tt, 1.0f)); }
                        { float dv = v0 - Cv; float tt = dv * wa; ge += tt * rsqrtf(fmaf(dv, tt, 1.0f)); }
                        if (j != 4) {
                            const float wb = (d2 == 1) ? w1 : w2;
                            float dv = v0 - Bv; float tt = dv * wb;
                            ge += tt * rsqrtf(fmaf(dv, tt, 1.0f));
                        }
                    }
                }
                float gd = 0.f;
                #pragma unroll
                for (int dz = 0; dz < 5; ++dz) {
                    int zz = zz0 + dz - 2;
                    if ((unsigned)zz < (unsigned)D && (zz % stride) == 0) {
                        int pi = zz / stride;
                        if (pi < NS) gd = fmaf(d_p[dz], Ecol[pi * HW], gd);
                    }
                }
                float xn = v0 - ALPHA * (gd + BETA * ge);
                if (do_relu) xn = fmaxf(xn, 0.f);
                outcol[zz0 * HW] = xn;
            }
            __syncthreads();
        }
    }
}

// ===========================================================================
// Generic fallback kernels (runtime dims) — validated in R4/R5.
// ===========================================================================

__global__ __launch_bounds__(256) void fused_E_gen(
    const float* __restrict__ x, const float* __restrict__ slices,
    float* __restrict__ E, const int* __restrict__ stridep,
    int D, int H, int W, int n_slices) {
    __shared__ float sZ[40][44];
    __shared__ float sA[40][36];
    __shared__ float sF[36][36];
    __shared__ float sB[36][33];

    const int i = blockIdx.z;
    const int zi = i * (*stridep);
    const int x0 = blockIdx.x * 32, y0 = blockIdx.y * 32;
    const int tx = threadIdx.x, ty = threadIdx.y;
    const size_t HW = (size_t)H * W;

    const float p0 = d_p[0], p1 = d_p[1], p2 = d_p[2], p3 = d_p[3], p4 = d_p[4];

    {
        const int z0 = zi - 2;
        const bool zok0 = (z0 >= 0), zok1 = (z0 + 1 >= 0);
        const bool zok2 = (z0 + 2 >= 0) && (z0 + 2 < D);
        const bool zok3 = (z0 + 3 < D), zok4 = (z0 + 4 < D);
        #pragma unroll
        for (int k = 0; k < 5; ++k) {
            const int r = ty + 8 * k;
            const int gy = y0 - 4 + r;
            const bool okY = (unsigned)gy < (unsigned)H;
            #pragma unroll
            for (int b = 0; b < 2; ++b) {
                const int c = b * 32 + tx;
                if (b == 1 && tx >= 8) break;
                const int gx = x0 - 4 + c;
                float acc = 0.f;
                if (okY && (unsigned)gx < (unsigned)W) {
                    const float* col = x + (size_t)gy * W + gx + (size_t)z0 * HW;
                    if (zok0) acc = fmaf(p0, col[0], acc);
                    if (zok1) acc = fmaf(p1, col[HW], acc);
                    if (zok2) acc = fmaf(p2, col[2 * HW], acc);
                    if (zok3) acc = fmaf(p3, col[3 * HW], acc);
                    if (zok4) acc = fmaf(p4, col[4 * HW], acc);
                }
                sZ[r][c] = acc;
            }
        }
    }
    __syncthreads();

    #pragma unroll
    for (int k = 0; k < 5; ++k) {
        const int r = ty + 8 * k;
        sA[r][tx] = p0 * sZ[r][tx]     + p1 * sZ[r][tx + 1] + p2 * sZ[r][tx + 2]
                  + p3 * sZ[r][tx + 3] + p4 * sZ[r][tx + 4];
        if (tx < 4) {
            const int c = 32 + tx;
            sA[r][c] = p0 * sZ[r][c]     + p1 * sZ[r][c + 1] + p2 * sZ[r][c + 2]
                     + p3 * sZ[r][c + 3] + p4 * sZ[r][c + 4];
        }
    }
    __syncthreads();

    {
        const float* sl = slices + (size_t)i * HW;
        #pragma unroll
        for (int k = 0; k < 5; ++k) {
            const int r = (k < 4) ? (ty + 8 * k) : (32 + ty);
            if (k == 4 && ty >= 4) break;
            const int gy = y0 - 2 + r;
            const bool okY = (unsigned)gy < (unsigned)H;
            #pragma unroll
            for (int b = 0; b < 2; ++b) {
                const int c = b * 32 + tx;
                if (b == 1 && tx >= 4) break;
                const int gx = x0 - 2 + c;
                float v = 0.f;
                if (okY && (unsigned)gx < (unsigned)W) {
                    v = p0 * sA[r][c]     + p1 * sA[r + 1][c] + p2 * sA[r + 2][c]
                      + p3 * sA[r + 3][c] + p4 * sA[r + 4][c]
                      - sl[(size_t)gy * W + gx];
                }
                sF[r][c] = v;
            }
        }
    }
    __syncthreads();

    #pragma unroll
    for (int k = 0; k < 5; ++k) {
        const int r = (k < 4) ? (ty + 8 * k) : (32 + ty);
        if (k == 4 && ty >= 4) break;
        sB[r][tx] = p0 * sF[r][tx]     + p1 * sF[r][tx + 1] + p2 * sF[r][tx + 2]
                  + p3 * sF[r][tx + 3] + p4 * sF[r][tx + 4];
    }
    __syncthreads();

    {
        float* Ei = E + (size_t)i * HW;
        #pragma unroll
        for (int k = 0; k < 4; ++k) {
            const int r = ty + 8 * k;
            const int gy = y0 + r, gx = x0 + tx;
            if (gy < H && gx < W) {
                Ei[(size_t)gy * W + gx] =
                      p0 * sB[r][tx]     + p1 * sB[r + 1][tx] + p2 * sB[r + 2][tx]
                    + p3 * sB[r + 3][tx] + p4 * sB[r + 4][tx];
            }
        }
    }
}

__global__ __launch_bounds__(256, 4) void update_gen(
    const float* __restrict__ xin, const float* __restrict__ E,
    float* __restrict__ xout, const int* __restrict__ stridep,
    int n_slices, int D, int H, int W, int do_relu) {
    __shared__ float s[3][10][36];

    const int x0 = blockIdx.x * 32, y0 = blockIdx.y * 8;
    const int zb = blockIdx.z * UPD_CHUNK;
    const int tx = threadIdx.x, ty = threadIdx.y;
    const int tid = ty * 32 + tx;
    const size_t HW = (size_t)H * W;
    const int y = y0 + ty, x = x0 + tx;
    const int stride = *stridep;

    const float p0 = d_p[0], p1 = d_p[1], p2 = d_p[2], p3 = d_p[3], p4 = d_p[4];
    const float pz[5] = {p0, p1, p2, p3, p4};
    const float w1 = (float)(1.0 / (1.0 * 0.1 * 0.1));
    const float w2 = (float)(1.0 / (2.0 * 0.1 * 0.1));
    const float w3 = (float)(1.0 / (3.0 * 0.1 * 0.1));

    const int ly0 = tid / 34, lx0 = tid % 34;
    const int gy0 = y0 - 1 + ly0, gx0 = x0 - 1 + lx0;
    const bool ok0 = (unsigned)gy0 < (unsigned)H && (unsigned)gx0 < (unsigned)W;
    const size_t off0 = ok0 ? ((size_t)gy0 * W + gx0) : 0;
    const int i1 = tid + 256;
    const bool has1 = (i1 < 340);
    const int ly1 = has1 ? i1 / 34 : 0, lx1 = has1 ? i1 % 34 : 0;
    const int gy1 = y0 - 1 + ly1, gx1 = x0 - 1 + lx1;
    const bool ok1 = has1 && (unsigned)gy1 < (unsigned)H && (unsigned)gx1 < (unsigned)W;
    const size_t off1 = ok1 ? ((size_t)gy1 * W + gx1) : 0;

    auto loadPlane = [&](int z, int sl) {
        const bool zok = (unsigned)z < (unsigned)D;
        const size_t zo = (size_t)(zok ? z : 0) * HW;
        s[sl][ly0][lx0] = (zok && ok0) ? xin[zo + off0] : 0.f;
        if (has1) s[sl][ly1][lx1] = (zok && ok1) ? xin[zo + off1] : 0.f;
    };

    const int sl_m1 = ((zb - 1) % 3 + 3) % 3;
    const int sl_0  = zb % 3;
    loadPlane(zb - 1, sl_m1);
    loadPlane(zb, sl_0);
    __syncthreads();

    float A[9], B[9];
    #pragma unroll
    for (int dy = 0; dy < 3; ++dy)
        #pragma unroll
        for (int dx = 0; dx < 3; ++dx) {
            A[dy * 3 + dx] = s[sl_m1][ty + dy][tx + dx];
            B[dy * 3 + dx] = s[sl_0][ty + dy][tx + dx];
        }

    const bool interior_xy = (y > 0 && y < H - 1 && x > 0 && x < W - 1);
    const size_t eo = (size_t)y * W + x;
    const float* Ecol = E + eo;
    float* outcol = xout + eo;
    const float ALPHA = 0.5f;
    const float BETA = (float)(0.02 * 0.1 * 0.1);

    int zend = zb + UPD_CHUNK;
    if (zend > D) zend = D;

    for (int z = zb; z < zend; ++z) {
        const int sl = (z + 1) % 3;
        loadPlane(z + 1, sl);
        __syncthreads();

        float C[9];
        #pragma unroll
        for (int dy = 0; dy < 3; ++dy)
            #pragma unroll
            for (int dx = 0; dx < 3; ++dx)
                C[dy * 3 + dx] = s[sl][ty + dy][tx + dx];

        const float v0 = B[4];
        float gd = 0.f;
        #pragma unroll
        for (int dz = 0; dz < 5; ++dz) {
            int zz = z + dz - 2;
            if ((unsigned)zz < (unsigned)D && (zz % stride) == 0) {
                int pi = zz / stride;
                if (pi < n_slices) gd = fmaf(pz[dz], Ecol[(size_t)pi * HW], gd);
            }
        }

        float greg = 0.f;
        if (interior_xy && z > 0 && z < D - 1) {
            #pragma unroll
            for (int j = 0; j < 9; ++j) {
                const int dy = j / 3 - 1, dx = j % 3 - 1;
                const int d2a = dy * dy + dx * dx + 1;
                const float wa = (d2a == 1) ? w1 : ((d2a == 2) ? w2 : w3);
                { float dv = v0 - A[j]; float t = dv * wa; greg += t * rsqrtf(fmaf(dv, t, 1.0f)); }
                { float dv = v0 - C[j]; float t = dv * wa; greg += t * rsqrtf(fmaf(dv, t, 1.0f)); }
                if (j != 4) {
                    const int d2b = dy * dy + dx * dx;
                    const float wb = (d2b == 1) ? w1 : ((d2b == 2) ? w2 : w3);
                    float dv = v0 - B[j]; float t = dv * wb;
                    greg += t * rsqrtf(fmaf(dv, t, 1.0f));
                }
            }
        }

        float xn = v0 - ALPHA * (gd + BETA * greg);
        if (do_relu) xn = fmaxf(xn, 0.f);
        outcol[(size_t)z * HW] = xn;

        #pragma unroll
        for (int j = 0; j < 9; ++j) { A[j] = B[j]; B[j] = C[j]; }
    }
}

// ---------------------------------------------------------------------------
extern "C" void kernel_launch(void* const* d_in, const int* in_sizes, int n_in,
                              void* d_out, int out_size) {
    const float* slices = (const float*)d_in[1];
    const float* volume = (const float*)d_in[2];
    const float* psf    = (const float*)d_in[3];
    const int* stridep  = (const int*)d_in[4];

    int D = (int)lround(cbrt((double)out_size));   // 192
    int H = D, W = D;
    int n_slices = in_sizes[1] / (H * W);

    float *pE, *pA, *pB;
    cudaGetSymbolAddress((void**)&pE, d_E);
    cudaGetSymbolAddress((void**)&pA, d_A);
    cudaGetSymbolAddress((void**)&pB, d_B);

    init_p_kernel<<<1, 32>>>(psf);

    const bool spec = (D == 192 && H == 192 && W == 192 && n_slices == 96);

    dim3 blkE(32, 8, 1);
    dim3 grid_E2((W + 31) / 32, (H + 31) / 32, n_slices / 2);
    dim3 grid_E((W + 31) / 32, (H + 31) / 32, n_slices);
    dim3 blkU(32, 8, 1);
    dim3 grid_up((W + 31) / 32, (H + 7) / 8, (D + UPD_CHUNK - 1) / UPD_CHUNK);

    if (spec) {
        stilde_t<192, 192><<<dim3(6, 6, 96), blkE>>>(slices, pB);
        for (int it = 0; it < N_ITER; ++it) {
            const float* xin = (it == 0) ? volume
                                         : ((it & 1) ? pA : (const float*)d_out);
            float* xout = (it & 1) ? (float*)d_out : pA;
            int do_relu = (it == N_ITER - 1) ? 1 : 0;
            fused_E3_t<192, 192, 192, 96><<<grid_E2, blkE>>>(xin, pB, pE, stridep);
            update4_t<192, 192, 192, 96><<<grid_up, blkU>>>(xin, pE, xout, stridep, do_relu);
        }
    } else {
        for (int it = 0; it < N_ITER; ++it) {
            const float* xin = (it == 0) ? volume : ((it & 1) ? pA : pB);
            float* xout = (it == N_ITER - 1) ? (float*)d_out
                                             : ((it & 1) ? pB : pA);
            int do_relu = (it == N_ITER - 1) ? 1 : 0;
            fused_E_gen<<<grid_E, blkE>>>(xin, slices, pE, stridep, D, H, W, n_slices);
            update_gen<<<grid_up, blkU>>>(xin, pE, xout, stridep, n_slices, D, H, W, do_relu);
        }
    }
}